// round 4
// baseline (speedup 1.0000x reference)
#include <cuda_runtime.h>

// ---------------- problem constants (fixed shapes for this dataset) --------
#define B_    16
#define M_    32768
#define K_    85
#define KP    96            // K padded to 16*6 for the register tiling
#define NF_   64
#define DO_   16
#define NCH   32            // chunks per batch (kernel A)
#define CHPT  (M_ / NCH)    // 1024 points per chunk
#define PT    32            // points per smem tile in kernel A
#define PPB_D 256           // points per block in kernel D
#define OUTW  (NF_ + DO_)   // 80

typedef unsigned long long ull;

// ---------------- scratch (device globals: the sanctioned no-alloc path) ---
// 16B-aligned: written/read with 128-bit vector ops.
__device__ __align__(16) float g_qf_partial[B_ * NCH * KP * NF_];   // ~12.6 MB
__device__ __align__(16) float g_P[B_ * K_ * DO_];

__device__ __forceinline__ float ex2f(float x) {
    float y;
    asm("ex2.approx.ftz.f32 %0, %1;" : "=f"(y) : "f"(x));
    return y;
}

// packed fp32x2 FMA (Blackwell FFMA2; ptxas never auto-fuses — PTX only)
__device__ __forceinline__ void fma2(ull& d, ull a, ull b) {
    asm("fma.rn.f32x2 %0, %1, %2, %0;" : "+l"(d) : "l"(a), "l"(b));
}
__device__ __forceinline__ ull splat2(float x) {
    ull d; unsigned u = __float_as_uint(x);
    asm("mov.b64 %0, {%1, %1};" : "=l"(d) : "r"(u));
    return d;
}

#define LOG2E 1.4426950408889634f

// ===========================================================================
// Kernel A: partial QF[b,k,f] = sum_m qd(m,k) * F[m,f]*omegaF[f]
// grid (NCH, B_), 256 threads. Thread (tk,tf) in 16x16 owns a 6(k) x 4(f)
// tile of the 96x64 accumulator, held as 6x2 packed f32x2 registers.
// qd is stored DUPLICATED in smem so the k-operand splat is a plain LDS.
// ===========================================================================
__global__ __launch_bounds__(256, 2)
void kA(const float* __restrict__ X, const float* __restrict__ F,
        const float* __restrict__ QX, const float* __restrict__ omD,
        const float* __restrict__ omF)
{
    __shared__ float s_qx0[KP], s_qx1[KP], s_qx2[KP], s_c[KP], s_s[KP];
    __shared__ __align__(16) float s_of[NF_];
    __shared__ float s_x[PT][4];                         // x,y,z,x2
    __shared__ __align__(16) float s_qd2[PT][KP][2];     // duplicated qd
    __shared__ __align__(16) float s_f[PT][NF_];

    const int tid = threadIdx.x;
    const int b   = blockIdx.y;
    const int ch  = blockIdx.x;
    const long base = (long)b * M_ + (long)ch * CHPT;

    // per-k folded constants: arg = c_k - s_k*x2 + qx'.x  (pre-scaled by log2e)
    if (tid < KP) {
        float qx = 0.f, qy = 0.f, qz = 0.f, sk = 0.f, ck = -1e30f; // pad -> qd=0
        if (tid < K_) {
            qx = QX[tid * 3 + 0]; qy = QX[tid * 3 + 1]; qz = QX[tid * 3 + 2];
            float om  = omD[tid];
            float inv = 1.0f / (om * om);
            float q2  = qx * qx + qy * qy + qz * qz;
            sk = inv * LOG2E;
            ck = -q2 * inv * LOG2E;
            float t = 2.0f * inv * LOG2E;
            qx *= t; qy *= t; qz *= t;
        }
        s_qx0[tid] = qx; s_qx1[tid] = qy; s_qx2[tid] = qz;
        s_s[tid] = sk;   s_c[tid] = ck;
    }
    if (tid < NF_) s_of[tid] = omF[tid];

    const int tk6 = (tid >> 4) * 6;  // k rows tk6 .. tk6+5 (byte off 48*tk -> 16B ok)
    const int tf  = tid & 15;        // f cols tf*4 .. tf*4+3

    ull acc[6][2];
#pragma unroll
    for (int i = 0; i < 6; i++) { acc[i][0] = 0ull; acc[i][1] = 0ull; }

    __syncthreads();

    for (int t0 = 0; t0 < CHPT; t0 += PT) {
        // ---- phase 1: stage X and omegaF-scaled F ----
        if (tid < PT) {
            const float* xp = X + (base + t0 + tid) * 3;
            float x = xp[0], y = xp[1], z = xp[2];
            s_x[tid][0] = x; s_x[tid][1] = y; s_x[tid][2] = z;
            s_x[tid][3] = x * x + y * y + z * z;
        }
        {
            const float4* fp  = (const float4*)(F + (base + t0) * NF_);
            float4*       sf4 = (float4*)&s_f[0][0];
            const float4* of4 = (const float4*)s_of;
#pragma unroll
            for (int i = 0; i < (PT * NF_ / 4) / 256; i++) {
                int e = tid + i * 256;
                float4 fv = fp[e];
                float4 ov = of4[e & 15];
                fv.x *= ov.x; fv.y *= ov.y; fv.z *= ov.z; fv.w *= ov.w;
                sf4[e] = fv;
            }
        }
        __syncthreads();

        // ---- phase 2: compute duplicated qd tile ----
        {
            const int pt = tid >> 3;          // 32 points x 8 threads
            const int kb = tid & 7;
            float x  = s_x[pt][0], y = s_x[pt][1], z = s_x[pt][2], x2 = s_x[pt][3];
#pragma unroll
            for (int j = 0; j < KP / 8; j++) {
                int k = kb + j * 8;
                float arg = fmaf(s_qx2[k], z,
                            fmaf(s_qx1[k], y,
                            fmaf(s_qx0[k], x,
                            fmaf(-s_s[k], x2, s_c[k]))));
                float qd = ex2f(arg);         // pad rows: c=-1e30 -> 0
                float2 w; w.x = qd; w.y = qd;
                *(float2*)&s_qd2[pt][k][0] = w;   // 8B-aligned (base 16B, k*8)
            }
        }
        __syncthreads();

        // ---- phase 3: rank-PT update, packed f32x2 ----
#pragma unroll 8
        for (int p = 0; p < PT; ++p) {
            const ulonglong2* aq = (const ulonglong2*)&s_qd2[p][tk6][0]; // 16B ok
            ulonglong2 a01 = aq[0], a23 = aq[1], a45 = aq[2];            // splatted
            ulonglong2 bb  = *(const ulonglong2*)&s_f[p][tf * 4];        // 16B ok
            fma2(acc[0][0], a01.x, bb.x); fma2(acc[0][1], a01.x, bb.y);
            fma2(acc[1][0], a01.y, bb.x); fma2(acc[1][1], a01.y, bb.y);
            fma2(acc[2][0], a23.x, bb.x); fma2(acc[2][1], a23.x, bb.y);
            fma2(acc[3][0], a23.y, bb.x); fma2(acc[3][1], a23.y, bb.y);
            fma2(acc[4][0], a45.x, bb.x); fma2(acc[4][1], a45.x, bb.y);
            fma2(acc[5][0], a45.y, bb.x); fma2(acc[5][1], a45.y, bb.y);
        }
        __syncthreads();
    }

    // ---- epilogue: write the 96x64 partial (coalesced float4) ----
    const int part = b * NCH + ch;
#pragma unroll
    for (int i = 0; i < 6; i++) {
        int k = tk6 + i;
        float2 lo = *(float2*)&acc[i][0];
        float2 hi = *(float2*)&acc[i][1];
        float4 v = make_float4(lo.x, lo.y, hi.x, hi.y);
        *(float4*)&g_qf_partial[((long)part * KP + k) * NF_ + tf * 4] = v;
    }
}

// ===========================================================================
// Kernel B: reduce partials over chunks, project through QW -> P[b,k,0:16]
// grid (K_, B_), 64 threads.
// ===========================================================================
__global__ __launch_bounds__(64)
void kB(const float* __restrict__ QW)
{
    const int k = blockIdx.x, b = blockIdx.y, f = threadIdx.x;
    const float* p = g_qf_partial + ((long)(b * NCH) * KP + k) * NF_ + f;
    float s = 0.f;
#pragma unroll
    for (int c = 0; c < NCH; c++) s += p[(long)c * KP * NF_];

    __shared__ float sq[NF_];
    sq[f] = s;
    __syncthreads();

    if (f < DO_) {
        float a = 0.f;
#pragma unroll
        for (int j = 0; j < NF_; j++) a = fmaf(sq[j], QW[j * DO_ + f], a);
        g_P[(b * K_ + k) * DO_ + f] = a;
    }
}

// ===========================================================================
// Kernel D: QY[m,:] = sum_k qd(m,k) * P[k,:]; out = concat(F, QY)
// grid (M_/PPB_D, B_), 256 threads (one point each) with packed f32x2
// accumulators, then a cooperative fully-coalesced 80-wide output write.
// ===========================================================================
__global__ __launch_bounds__(256, 2)
void kD(const float* __restrict__ X, const float* __restrict__ F,
        const float* __restrict__ QX, const float* __restrict__ omD,
        float* __restrict__ out)
{
    __shared__ float s_qx0[K_], s_qx1[K_], s_qx2[K_], s_c[K_], s_s[K_];
    __shared__ __align__(16) float s_P[K_][DO_];          // rows 64B
    __shared__ __align__(16) float s_y[PPB_D][DO_ + 2];   // rows 72B (8B-mult)

    const int tid = threadIdx.x;
    const int b   = blockIdx.y;
    const long base = (long)b * M_ + (long)blockIdx.x * PPB_D;

    if (tid < K_) {
        float qx = QX[tid * 3 + 0], qy = QX[tid * 3 + 1], qz = QX[tid * 3 + 2];
        float om  = omD[tid];
        float inv = 1.0f / (om * om);
        float q2  = qx * qx + qy * qy + qz * qz;
        s_s[tid] = inv * LOG2E;
        s_c[tid] = -q2 * inv * LOG2E;
        float t = 2.0f * inv * LOG2E;
        s_qx0[tid] = qx * t; s_qx1[tid] = qy * t; s_qx2[tid] = qz * t;
    }
    for (int e = tid; e < K_ * DO_; e += 256)
        (&s_P[0][0])[e] = g_P[(long)b * K_ * DO_ + e];
    __syncthreads();

    // ---- per-point accumulate against smem-resident P (packed) ----
    {
        const float* xp = X + (base + tid) * 3;
        float x = xp[0], y = xp[1], z = xp[2];
        float x2 = x * x + y * y + z * z;

        ull acc[8];
#pragma unroll
        for (int d = 0; d < 8; d++) acc[d] = 0ull;

#pragma unroll 5
        for (int k = 0; k < K_; k++) {
            float arg = fmaf(s_qx2[k], z,
                        fmaf(s_qx1[k], y,
                        fmaf(s_qx0[k], x,
                        fmaf(-s_s[k], x2, s_c[k]))));
            ull qd2 = splat2(ex2f(arg));
            const ulonglong2* pr = (const ulonglong2*)&s_P[k][0];  // 16B ok; bcast
            ulonglong2 q0 = pr[0], q1 = pr[1];
            fma2(acc[0], qd2, q0.x); fma2(acc[1], qd2, q0.y);
            fma2(acc[2], qd2, q1.x); fma2(acc[3], qd2, q1.y);
            ulonglong2 q2_ = pr[2], q3 = pr[3];
            fma2(acc[4], qd2, q2_.x); fma2(acc[5], qd2, q2_.y);
            fma2(acc[6], qd2, q3.x);  fma2(acc[7], qd2, q3.y);
        }
#pragma unroll
        for (int d = 0; d < 8; d++)
            *(float2*)&s_y[tid][2 * d] = *(float2*)&acc[d];  // 8B-aligned
    }
    __syncthreads();

    // ---- cooperative coalesced write: 256 points x 80 floats = 5120 float4 ----
    const float4* f4 = (const float4*)(F + base * NF_);
    float4*       o4 = (float4*)(out + base * OUTW);
#pragma unroll
    for (int i = 0; i < (PPB_D * OUTW / 4) / 256; i++) {
        int e  = tid + i * 256;
        int pt = e / (OUTW / 4);              // /20 (const)
        int c  = e % (OUTW / 4);
        float4 v;
        if (c < NF_ / 4) {
            v = f4[pt * (NF_ / 4) + c];       // forward input features
        } else {
            int d = (c - NF_ / 4) * 4;
            v = make_float4(s_y[pt][d], s_y[pt][d + 1], s_y[pt][d + 2], s_y[pt][d + 3]);
        }
        o4[e] = v;
    }
}

// ===========================================================================
extern "C" void kernel_launch(void* const* d_in, const int* in_sizes, int n_in,
                              void* d_out, int out_size)
{
    const float* X   = (const float*)d_in[0];
    const float* F   = (const float*)d_in[1];
    const float* QX  = (const float*)d_in[2];
    const float* omD = (const float*)d_in[3];
    const float* omF = (const float*)d_in[4];
    const float* QW  = (const float*)d_in[5];
    float* out = (float*)d_out;

    kA<<<dim3(NCH, B_), 256>>>(X, F, QX, omD, omF);
    kB<<<dim3(K_, B_), 64>>>(QW);
    kD<<<dim3(M_ / PPB_D, B_), 256>>>(X, F, QX, omD, out);
}

// round 5
// speedup vs baseline: 1.1363x; 1.1363x over previous
#include <cuda_runtime.h>

// ---------------- problem constants (fixed shapes for this dataset) --------
#define B_    16
#define M_    32768
#define K_    85
#define KP    96            // K padded to 16*6 for the register tiling
#define NF_   64
#define DO_   16
#define NCH   64            // chunks per batch (kernel A)
#define CHPT  (M_ / NCH)    // 512 points per chunk
#define PT    32            // points per smem tile in kernel A
#define KAT   128           // kA threads per block
#define QROW  (KP * 2 + 4)  // padded dup-qd row (words): kills STS bank conflicts
#define PPB_D 256           // points per block in kernel D
#define OUTW  (NF_ + DO_)   // 80

typedef unsigned long long ull;

// ---------------- scratch (device globals: the sanctioned no-alloc path) ---
__device__ __align__(16) float g_qf_partial[B_ * NCH * KP * NF_];   // ~25 MB
__device__ __align__(16) float g_P[B_ * K_ * DO_];

__device__ __forceinline__ float ex2f(float x) {
    float y;
    asm("ex2.approx.ftz.f32 %0, %1;" : "=f"(y) : "f"(x));
    return y;
}

// packed fp32x2 FMA (Blackwell FFMA2; ptxas never auto-fuses — PTX only)
__device__ __forceinline__ void fma2(ull& d, ull a, ull b) {
    asm("fma.rn.f32x2 %0, %1, %2, %0;" : "+l"(d) : "l"(a), "l"(b));
}
__device__ __forceinline__ ull splat2(float x) {
    ull d; unsigned u = __float_as_uint(x);
    asm("mov.b64 %0, {%1, %1};" : "=l"(d) : "r"(u));
    return d;
}

#define LOG2E 1.4426950408889634f

// ===========================================================================
// Kernel A: partial QF[b,k,f] = sum_m qd(m,k) * F[m,f]*omegaF[f]
// grid (NCH, B_), 128 threads. Thread (tk,tf) in 16x8 owns a 6(k) x 8(f)
// tile of the 96x64 accumulator as 6x4 packed f32x2 registers.
// Per p: 3 broadcast LDS (dup'd qd) + 2 LDS.128 (f) feed 24 FFMA2 -> FMA-bound.
// ===========================================================================
__global__ __launch_bounds__(KAT, 4)
void kA(const float* __restrict__ X, const float* __restrict__ F,
        const float* __restrict__ QX, const float* __restrict__ omD,
        const float* __restrict__ omF)
{
    __shared__ __align__(16) float4 s_cst[KP];           // qx',qy',qz',s
    __shared__ float s_c[KP];
    __shared__ __align__(16) float s_of[NF_];
    __shared__ __align__(16) float s_x[PT][4];           // x,y,z,x2
    __shared__ __align__(16) float s_qd2[PT][QROW];      // dup'd qd, padded rows
    __shared__ __align__(16) float s_f[PT][NF_];

    const int tid = threadIdx.x;
    const int b   = blockIdx.y;
    const int ch  = blockIdx.x;
    const long base = (long)b * M_ + (long)ch * CHPT;

    // per-k folded constants: arg = c_k - s_k*x2 + qx'.x  (pre-scaled by log2e)
    if (tid < KP) {
        float qx = 0.f, qy = 0.f, qz = 0.f, sk = 0.f, ck = -1e30f; // pad -> qd=0
        if (tid < K_) {
            qx = QX[tid * 3 + 0]; qy = QX[tid * 3 + 1]; qz = QX[tid * 3 + 2];
            float om  = omD[tid];
            float inv = 1.0f / (om * om);
            float q2  = qx * qx + qy * qy + qz * qz;
            sk = inv * LOG2E;
            ck = -q2 * inv * LOG2E;
            float t = 2.0f * inv * LOG2E;
            qx *= t; qy *= t; qz *= t;
        }
        s_cst[tid] = make_float4(qx, qy, qz, sk);
        s_c[tid]   = ck;
    }
    if (tid < NF_) s_of[tid] = omF[tid];

    const int tk6 = (tid >> 3) * 6;  // k rows tk6 .. tk6+5
    const int tf8 = (tid & 7) * 8;   // f cols tf8 .. tf8+7

    ull acc[6][4];
#pragma unroll
    for (int i = 0; i < 6; i++)
#pragma unroll
        for (int j = 0; j < 4; j++) acc[i][j] = 0ull;

    __syncthreads();

    for (int t0 = 0; t0 < CHPT; t0 += PT) {
        // ---- phase 1: stage X and omegaF-scaled F ----
        if (tid < PT) {
            const float* xp = X + (base + t0 + tid) * 3;
            float x = xp[0], y = xp[1], z = xp[2];
            s_x[tid][0] = x; s_x[tid][1] = y; s_x[tid][2] = z;
            s_x[tid][3] = x * x + y * y + z * z;
        }
        {
            const float4* fp  = (const float4*)(F + (base + t0) * NF_);
            float4*       sf4 = (float4*)&s_f[0][0];
            const float4* of4 = (const float4*)s_of;
#pragma unroll
            for (int i = 0; i < (PT * NF_ / 4) / KAT; i++) {  // 4 iters
                int e = tid + i * KAT;
                float4 fv = fp[e];
                float4 ov = of4[e & 15];
                fv.x *= ov.x; fv.y *= ov.y; fv.z *= ov.z; fv.w *= ov.w;
                sf4[e] = fv;
            }
        }
        __syncthreads();

        // ---- phase 2: compute duplicated qd tile (bank-spread mapping) ----
        {
            const int p  = tid >> 2;          // 32 points x 4 threads
            const int kb = tid & 3;
            float4 xv = *(const float4*)&s_x[p][0];   // x,y,z,x2 (broadcast)
#pragma unroll
            for (int j = 0; j < KP / 4; j++) {        // 24 k's per thread
                int k = kb + j * 4;
                float4 cst = s_cst[k];
                float arg = fmaf(cst.z, xv.z,
                            fmaf(cst.y, xv.y,
                            fmaf(cst.x, xv.x,
                            fmaf(-cst.w, xv.w, s_c[k]))));
                float qd = ex2f(arg);                 // pad rows: c=-1e30 -> 0
                float2 w; w.x = qd; w.y = qd;
                *(float2*)&s_qd2[p][2 * k] = w;       // 8B-aligned
            }
        }
        __syncthreads();

        // ---- phase 3: rank-PT update, packed f32x2, 6k x 8f per thread ----
#pragma unroll 4
        for (int p = 0; p < PT; ++p) {
            const ulonglong2* aq = (const ulonglong2*)&s_qd2[p][2 * tk6]; // 16B ok
            ulonglong2 a01 = aq[0], a23 = aq[1], a45 = aq[2];             // dup'd
            ulonglong2 b01 = *(const ulonglong2*)&s_f[p][tf8];
            ulonglong2 b23 = *(const ulonglong2*)&s_f[p][tf8 + 4];
            fma2(acc[0][0], a01.x, b01.x); fma2(acc[0][1], a01.x, b01.y);
            fma2(acc[0][2], a01.x, b23.x); fma2(acc[0][3], a01.x, b23.y);
            fma2(acc[1][0], a01.y, b01.x); fma2(acc[1][1], a01.y, b01.y);
            fma2(acc[1][2], a01.y, b23.x); fma2(acc[1][3], a01.y, b23.y);
            fma2(acc[2][0], a23.x, b01.x); fma2(acc[2][1], a23.x, b01.y);
            fma2(acc[2][2], a23.x, b23.x); fma2(acc[2][3], a23.x, b23.y);
            fma2(acc[3][0], a23.y, b01.x); fma2(acc[3][1], a23.y, b01.y);
            fma2(acc[3][2], a23.y, b23.x); fma2(acc[3][3], a23.y, b23.y);
            fma2(acc[4][0], a45.x, b01.x); fma2(acc[4][1], a45.x, b01.y);
            fma2(acc[4][2], a45.x, b23.x); fma2(acc[4][3], a45.x, b23.y);
            fma2(acc[5][0], a45.y, b01.x); fma2(acc[5][1], a45.y, b01.y);
            fma2(acc[5][2], a45.y, b23.x); fma2(acc[5][3], a45.y, b23.y);
        }
        __syncthreads();
    }

    // ---- epilogue: write the 96x64 partial (coalesced float4 pairs) ----
    const int part = b * NCH + ch;
#pragma unroll
    for (int i = 0; i < 6; i++) {
        int k = tk6 + i;
        float* dst = &g_qf_partial[((long)part * KP + k) * NF_ + tf8];
        float2 v0 = *(float2*)&acc[i][0];
        float2 v1 = *(float2*)&acc[i][1];
        float2 v2 = *(float2*)&acc[i][2];
        float2 v3 = *(float2*)&acc[i][3];
        *(float4*)(dst)     = make_float4(v0.x, v0.y, v1.x, v1.y);
        *(float4*)(dst + 4) = make_float4(v2.x, v2.y, v3.x, v3.y);
    }
}

// ===========================================================================
// Kernel B: reduce partials over chunks, project through QW -> P[b,k,0:16]
// grid (K_, B_), 64 threads.
// ===========================================================================
__global__ __launch_bounds__(64)
void kB(const float* __restrict__ QW)
{
    const int k = blockIdx.x, b = blockIdx.y, f = threadIdx.x;
    const float* p = g_qf_partial + ((long)(b * NCH) * KP + k) * NF_ + f;
    float s = 0.f;
#pragma unroll
    for (int c = 0; c < NCH; c++) s += p[(long)c * KP * NF_];

    __shared__ float sq[NF_];
    sq[f] = s;
    __syncthreads();

    if (f < DO_) {
        float a = 0.f;
#pragma unroll
        for (int j = 0; j < NF_; j++) a = fmaf(sq[j], QW[j * DO_ + f], a);
        g_P[(b * K_ + k) * DO_ + f] = a;
    }
}

// ===========================================================================
// Kernel D: QY[m,:] = sum_k qd(m,k) * P[k,:]; out = concat(F, QY)
// grid (M_/PPB_D, B_), 256 threads (one point each) with packed f32x2
// accumulators, then a cooperative fully-coalesced 80-wide output write.
// ===========================================================================
__global__ __launch_bounds__(256, 2)
void kD(const float* __restrict__ X, const float* __restrict__ F,
        const float* __restrict__ QX, const float* __restrict__ omD,
        float* __restrict__ out)
{
    __shared__ float s_qx0[K_], s_qx1[K_], s_qx2[K_], s_c[K_], s_s[K_];
    __shared__ __align__(16) float s_P[K_][DO_];          // rows 64B
    __shared__ __align__(16) float s_y[PPB_D][DO_ + 2];   // rows 72B (8B-mult)

    const int tid = threadIdx.x;
    const int b   = blockIdx.y;
    const long base = (long)b * M_ + (long)blockIdx.x * PPB_D;

    if (tid < K_) {
        float qx = QX[tid * 3 + 0], qy = QX[tid * 3 + 1], qz = QX[tid * 3 + 2];
        float om  = omD[tid];
        float inv = 1.0f / (om * om);
        float q2  = qx * qx + qy * qy + qz * qz;
        s_s[tid] = inv * LOG2E;
        s_c[tid] = -q2 * inv * LOG2E;
        float t = 2.0f * inv * LOG2E;
        s_qx0[tid] = qx * t; s_qx1[tid] = qy * t; s_qx2[tid] = qz * t;
    }
    for (int e = tid; e < K_ * DO_; e += 256)
        (&s_P[0][0])[e] = g_P[(long)b * K_ * DO_ + e];
    __syncthreads();

    // ---- per-point accumulate against smem-resident P (packed) ----
    {
        const float* xp = X + (base + tid) * 3;
        float x = xp[0], y = xp[1], z = xp[2];
        float x2 = x * x + y * y + z * z;

        ull acc[8];
#pragma unroll
        for (int d = 0; d < 8; d++) acc[d] = 0ull;

#pragma unroll 5
        for (int k = 0; k < K_; k++) {
            float arg = fmaf(s_qx2[k], z,
                        fmaf(s_qx1[k], y,
                        fmaf(s_qx0[k], x,
                        fmaf(-s_s[k], x2, s_c[k]))));
            ull qd2 = splat2(ex2f(arg));
            const ulonglong2* pr = (const ulonglong2*)&s_P[k][0];  // bcast
            ulonglong2 q0 = pr[0], q1 = pr[1];
            fma2(acc[0], qd2, q0.x); fma2(acc[1], qd2, q0.y);
            fma2(acc[2], qd2, q1.x); fma2(acc[3], qd2, q1.y);
            ulonglong2 q2_ = pr[2], q3 = pr[3];
            fma2(acc[4], qd2, q2_.x); fma2(acc[5], qd2, q2_.y);
            fma2(acc[6], qd2, q3.x);  fma2(acc[7], qd2, q3.y);
        }
#pragma unroll
        for (int d = 0; d < 8; d++)
            *(float2*)&s_y[tid][2 * d] = *(float2*)&acc[d];  // 8B-aligned
    }
    __syncthreads();

    // ---- cooperative coalesced write: 256 points x 80 floats = 5120 float4 ----
    const float4* f4 = (const float4*)(F + base * NF_);
    float4*       o4 = (float4*)(out + base * OUTW);
#pragma unroll
    for (int i = 0; i < (PPB_D * OUTW / 4) / 256; i++) {
        int e  = tid + i * 256;
        int pt = e / (OUTW / 4);              // /20 (const)
        int c  = e % (OUTW / 4);
        float4 v;
        if (c < NF_ / 4) {
            v = f4[pt * (NF_ / 4) + c];       // forward input features
        } else {
            int d = (c - NF_ / 4) * 4;
            v = make_float4(s_y[pt][d], s_y[pt][d + 1], s_y[pt][d + 2], s_y[pt][d + 3]);
        }
        o4[e] = v;
    }
}

// ===========================================================================
extern "C" void kernel_launch(void* const* d_in, const int* in_sizes, int n_in,
                              void* d_out, int out_size)
{
    const float* X   = (const float*)d_in[0];
    const float* F   = (const float*)d_in[1];
    const float* QX  = (const float*)d_in[2];
    const float* omD = (const float*)d_in[3];
    const float* omF = (const float*)d_in[4];
    const float* QW  = (const float*)d_in[5];
    float* out = (float*)d_out;

    kA<<<dim3(NCH, B_), KAT>>>(X, F, QX, omD, omF);
    kB<<<dim3(K_, B_), 64>>>(QW);
    kD<<<dim3(M_ / PPB_D, B_), 256>>>(X, F, QX, omD, out);
}

// round 7
// speedup vs baseline: 1.6224x; 1.4278x over previous
#include <cuda_runtime.h>

// ---------------- problem constants -----------------------------------------
#define B_    16
#define M_    32768
#define K_    85
#define KP    96            // kernel points padded to 8 pairs x 12
#define NF_   64
#define DO_   16
#define NCH   128           // chunks per batch (kernel A)
#define CHPT  (M_ / NCH)    // 256 points per chunk
#define PTS   32            // points per smem tile in kernel A
#define NTILE (CHPT / PTS)  // 8
#define QROW  100           // padded qd row (words)
#define PPD   512           // points per kD block (2 per thread)
#define OUTW  (NF_ + DO_)   // 80
#define LOG2E 1.4426950408889634f

typedef unsigned long long ull;
typedef unsigned int u32;

// ---------------- scratch (device globals: sanctioned no-alloc path) --------
__device__ __align__(16) float g_qf_partial[B_ * NCH * KP * NF_];   // ~50 MB
__device__ __align__(16) float g_P[B_ * K_ * DO_];

__device__ __forceinline__ float ex2f(float x) {
    float y; asm("ex2.approx.ftz.f32 %0, %1;" : "=f"(y) : "f"(x)); return y;
}
// packed fp32x2 FMA (FFMA2; ptxas never auto-fuses — PTX only)
__device__ __forceinline__ void fma2(ull& d, ull a, ull b) {
    asm("fma.rn.f32x2 %0, %1, %2, %0;" : "+l"(d) : "l"(a), "l"(b));
}
__device__ __forceinline__ ull splat2(float x) {
    ull d; u32 u = __float_as_uint(x);
    asm("mov.b64 %0, {%1, %1};" : "=l"(d) : "r"(u)); return d;
}

// ===========================================================================
// Kernel A: partial QF[b,ch,k,f] = sum_{p in chunk} qd(p,k) * F[p,f]*omF[f]
// 64 threads. Thread (kg,fg) in 8x8 owns 6 k-PAIRS x 8 f: accumulators are
// f32x2 over the k-pair lanes, so the a-operand is a plain float2 LDS of
// NON-duplicated qd (no splat); the b-operand is 8 register splats.
// Per p per thread: 3 LDS.128 (a) + 2 LDS.128 (b) = 80B for 96 FMA.
// ===========================================================================
__global__ __launch_bounds__(64, 6)
void kA(const float* __restrict__ X, const float* __restrict__ F,
        const float* __restrict__ QX, const float* __restrict__ omD,
        const float* __restrict__ omF)
{
    __shared__ __align__(16) float4 s_cst[KP];        // qx',qy',qz',s (log2e-scaled)
    __shared__ float s_c[KP];
    __shared__ __align__(16) float s_of[NF_];
    __shared__ __align__(16) float4 s_x[PTS];         // x,y,z,x2
    __shared__ __align__(16) float s_qd[PTS][QROW];   // qd rows (pad -> no conflicts)
    __shared__ __align__(16) float s_f[PTS][NF_];     // omegaF-scaled F tile

    const int tid = threadIdx.x;
    const int b   = blockIdx.y;
    const int ch  = blockIdx.x;
    const long base = (long)b * M_ + (long)ch * CHPT;

    // folded per-k constants: arg = c - s*x2 + qx'.x
    for (int e = tid; e < KP; e += 64) {
        float qx = 0.f, qy = 0.f, qz = 0.f, sk = 0.f, ck = -1e30f; // pad -> qd=0
        if (e < K_) {
            qx = QX[e * 3 + 0]; qy = QX[e * 3 + 1]; qz = QX[e * 3 + 2];
            float om = omD[e];
            float inv = 1.0f / (om * om);
            float q2 = qx * qx + qy * qy + qz * qz;
            sk = inv * LOG2E; ck = -q2 * inv * LOG2E;
            float tt = 2.0f * inv * LOG2E;
            qx *= tt; qy *= tt; qz *= tt;
        }
        s_cst[e] = make_float4(qx, qy, qz, sk);
        s_c[e]   = ck;
    }
    if (tid < NF_) s_of[tid] = omF[tid];
    // zero qd rows 88..95 once (phase 2 computes only 0..87; 85..87 -> ex2(-1e30)=0)
    for (int e = tid; e < PTS * 8; e += 64)
        s_qd[e >> 3][88 + (e & 7)] = 0.f;

    const int kg = tid >> 3;   // kpair-group: k rows kg*12 .. kg*12+11
    const int fg = tid & 7;    // f cols fg*8 .. fg*8+7

    ull acc[6][8];             // [kpair][f] : lanes = (k0,k1)
#pragma unroll
    for (int i = 0; i < 6; i++)
#pragma unroll
        for (int j = 0; j < 8; j++) acc[i][j] = 0ull;

    __syncthreads();

    for (int t = 0; t < NTILE; t++) {
        const long p0 = base + (long)t * PTS;

        // ---- phase 1: stage X and omegaF-scaled F (coalesced float4) ----
        if (tid < PTS) {
            const float* xp = X + (p0 + tid) * 3;
            float x = xp[0], y = xp[1], z = xp[2];
            s_x[tid] = make_float4(x, y, z, x * x + y * y + z * z);
        }
#pragma unroll
        for (int i = 0; i < 8; i++) {
            int e = tid + i * 64;
            int p = e >> 4, fq = e & 15;
            float4 fv = ((const float4*)(F + (p0 + p) * NF_))[fq];
            float4 ov = ((const float4*)s_of)[fq];
            fv.x *= ov.x; fv.y *= ov.y; fv.z *= ov.z; fv.w *= ov.w;
            *(float4*)&s_f[p][fq * 4] = fv;
        }
        __syncthreads();

        // ---- phase 2: qd tile, stored once (float2 pair stores) ----
        {
            const int p2 = tid >> 1;          // 32 points x 2 threads
            const int kh = (tid & 1) * 44;    // 44 k's each -> covers 0..87
            float4 xv = s_x[p2];
#pragma unroll
            for (int j = 0; j < 22; j++) {
                int k = kh + 2 * j;
                float4 c0 = s_cst[k], c1 = s_cst[k + 1];
                float a0 = fmaf(c0.z, xv.z, fmaf(c0.y, xv.y,
                           fmaf(c0.x, xv.x, fmaf(-c0.w, xv.w, s_c[k]))));
                float a1 = fmaf(c1.z, xv.z, fmaf(c1.y, xv.y,
                           fmaf(c1.x, xv.x, fmaf(-c1.w, xv.w, s_c[k + 1]))));
                float2 w; w.x = ex2f(a0); w.y = ex2f(a1);
                *(float2*)&s_qd[p2][k] = w;
            }
        }
        __syncthreads();

        // ---- phase 3: rank-PTS update, k-pair-packed f32x2 ----
#pragma unroll 2
        for (int p = 0; p < PTS; ++p) {
            const ulonglong2* ap = (const ulonglong2*)&s_qd[p][kg * 12]; // 16B ok
            ulonglong2 A0 = ap[0], A1 = ap[1], A2 = ap[2];  // 6 qd pairs
            const float4* bp = (const float4*)&s_f[p][fg * 8];
            float4 b0 = bp[0], b1 = bp[1];
            ull B0 = splat2(b0.x), B1 = splat2(b0.y), B2 = splat2(b0.z), B3 = splat2(b0.w);
            ull B4 = splat2(b1.x), B5 = splat2(b1.y), B6 = splat2(b1.z), B7 = splat2(b1.w);
            fma2(acc[0][0], A0.x, B0); fma2(acc[0][1], A0.x, B1);
            fma2(acc[0][2], A0.x, B2); fma2(acc[0][3], A0.x, B3);
            fma2(acc[0][4], A0.x, B4); fma2(acc[0][5], A0.x, B5);
            fma2(acc[0][6], A0.x, B6); fma2(acc[0][7], A0.x, B7);
            fma2(acc[1][0], A0.y, B0); fma2(acc[1][1], A0.y, B1);
            fma2(acc[1][2], A0.y, B2); fma2(acc[1][3], A0.y, B3);
            fma2(acc[1][4], A0.y, B4); fma2(acc[1][5], A0.y, B5);
            fma2(acc[1][6], A0.y, B6); fma2(acc[1][7], A0.y, B7);
            fma2(acc[2][0], A1.x, B0); fma2(acc[2][1], A1.x, B1);
            fma2(acc[2][2], A1.x, B2); fma2(acc[2][3], A1.x, B3);
            fma2(acc[2][4], A1.x, B4); fma2(acc[2][5], A1.x, B5);
            fma2(acc[2][6], A1.x, B6); fma2(acc[2][7], A1.x, B7);
            fma2(acc[3][0], A1.y, B0); fma2(acc[3][1], A1.y, B1);
            fma2(acc[3][2], A1.y, B2); fma2(acc[3][3], A1.y, B3);
            fma2(acc[3][4], A1.y, B4); fma2(acc[3][5], A1.y, B5);
            fma2(acc[3][6], A1.y, B6); fma2(acc[3][7], A1.y, B7);
            fma2(acc[4][0], A2.x, B0); fma2(acc[4][1], A2.x, B1);
            fma2(acc[4][2], A2.x, B2); fma2(acc[4][3], A2.x, B3);
            fma2(acc[4][4], A2.x, B4); fma2(acc[4][5], A2.x, B5);
            fma2(acc[4][6], A2.x, B6); fma2(acc[4][7], A2.x, B7);
            fma2(acc[5][0], A2.y, B0); fma2(acc[5][1], A2.y, B1);
            fma2(acc[5][2], A2.y, B2); fma2(acc[5][3], A2.y, B3);
            fma2(acc[5][4], A2.y, B4); fma2(acc[5][5], A2.y, B5);
            fma2(acc[5][6], A2.y, B6); fma2(acc[5][7], A2.y, B7);
        }
        __syncthreads();
    }

    // ---- epilogue: unpack k-pairs, write 96x64 partial (float4) ----
    const int part = b * NCH + ch;
#pragma unroll
    for (int i = 0; i < 6; i++) {
        int k0 = kg * 12 + 2 * i;
        float2 v0 = *(float2*)&acc[i][0], v1 = *(float2*)&acc[i][1];
        float2 v2 = *(float2*)&acc[i][2], v3 = *(float2*)&acc[i][3];
        float2 v4 = *(float2*)&acc[i][4], v5 = *(float2*)&acc[i][5];
        float2 v6 = *(float2*)&acc[i][6], v7 = *(float2*)&acc[i][7];
        float* d0 = &g_qf_partial[((long)part * KP + k0) * NF_ + fg * 8];
        *(float4*)(d0)       = make_float4(v0.x, v1.x, v2.x, v3.x);
        *(float4*)(d0 + 4)   = make_float4(v4.x, v5.x, v6.x, v7.x);
        float* d1 = d0 + NF_;
        *(float4*)(d1)       = make_float4(v0.y, v1.y, v2.y, v3.y);
        *(float4*)(d1 + 4)   = make_float4(v4.y, v5.y, v6.y, v7.y);
    }
}

// ===========================================================================
// Kernel B: reduce partials over chunks, project through QW -> P[b,k,0:16]
// ===========================================================================
__global__ __launch_bounds__(64)
void kB(const float* __restrict__ QW)
{
    const int k = blockIdx.x, b = blockIdx.y, f = threadIdx.x;
    const float* p = g_qf_partial + ((long)(b * NCH) * KP + k) * NF_ + f;
    float s = 0.f;
#pragma unroll 8
    for (int c = 0; c < NCH; c++) s += p[(long)c * KP * NF_];

    __shared__ float sq[NF_];
    sq[f] = s;
    __syncthreads();

    if (f < DO_) {
        float a = 0.f;
#pragma unroll
        for (int j = 0; j < NF_; j++) a = fmaf(sq[j], QW[j * DO_ + f], a);
        g_P[(b * K_ + k) * DO_ + f] = a;
    }
}

// ===========================================================================
// Kernel D: QY[m,:] = sum_k qd(m,k) * P[k,:]; out = concat(F, QY)
// 2 points per thread: P-row LDS amortized -> fma-bound.
// ===========================================================================
__global__ __launch_bounds__(256, 2)
void kD(const float* __restrict__ X, const float* __restrict__ F,
        const float* __restrict__ QX, const float* __restrict__ omD,
        float* __restrict__ out)
{
    __shared__ float s_qx0[K_], s_qx1[K_], s_qx2[K_], s_c[K_], s_s[K_];
    __shared__ __align__(16) float s_P[K_][DO_];        // rows 64B
    __shared__ __align__(16) float s_y[PPD][DO_ + 2];   // rows 72B

    const int tid = threadIdx.x;
    const int b   = blockIdx.y;
    const long base = (long)b * M_ + (long)blockIdx.x * PPD;

    if (tid < K_) {
        float qx = QX[tid * 3 + 0], qy = QX[tid * 3 + 1], qz = QX[tid * 3 + 2];
        float om = omD[tid];
        float inv = 1.0f / (om * om);
        float q2 = qx * qx + qy * qy + qz * qz;
        s_s[tid] = inv * LOG2E;
        s_c[tid] = -q2 * inv * LOG2E;
        float t = 2.0f * inv * LOG2E;
        s_qx0[tid] = qx * t; s_qx1[tid] = qy * t; s_qx2[tid] = qz * t;
    }
    for (int e = tid; e < K_ * DO_; e += 256)
        (&s_P[0][0])[e] = g_P[(long)b * K_ * DO_ + e];
    __syncthreads();

    {
        const int p0 = tid * 2;
        const float* xp = X + (base + p0) * 3;
        float xA = xp[0], yA = xp[1], zA = xp[2];
        float xB = xp[3], yB = xp[4], zB = xp[5];
        float x2A = xA * xA + yA * yA + zA * zA;
        float x2B = xB * xB + yB * yB + zB * zB;

        ull accA[8], accB[8];
#pragma unroll
        for (int d = 0; d < 8; d++) { accA[d] = 0ull; accB[d] = 0ull; }

#pragma unroll 5
        for (int k = 0; k < K_; k++) {
            float c0 = s_qx0[k], c1 = s_qx1[k], c2 = s_qx2[k];
            float sk = s_s[k], ck = s_c[k];
            float argA = fmaf(c2, zA, fmaf(c1, yA, fmaf(c0, xA, fmaf(-sk, x2A, ck))));
            float argB = fmaf(c2, zB, fmaf(c1, yB, fmaf(c0, xB, fmaf(-sk, x2B, ck))));
            ull qA = splat2(ex2f(argA));
            ull qB = splat2(ex2f(argB));
            const ulonglong2* pr = (const ulonglong2*)&s_P[k][0];  // broadcast
            ulonglong2 q0 = pr[0], q1 = pr[1];
            fma2(accA[0], qA, q0.x); fma2(accA[1], qA, q0.y);
            fma2(accA[2], qA, q1.x); fma2(accA[3], qA, q1.y);
            fma2(accB[0], qB, q0.x); fma2(accB[1], qB, q0.y);
            fma2(accB[2], qB, q1.x); fma2(accB[3], qB, q1.y);
            ulonglong2 q2_ = pr[2], q3 = pr[3];
            fma2(accA[4], qA, q2_.x); fma2(accA[5], qA, q2_.y);
            fma2(accA[6], qA, q3.x);  fma2(accA[7], qA, q3.y);
            fma2(accB[4], qB, q2_.x); fma2(accB[5], qB, q2_.y);
            fma2(accB[6], qB, q3.x);  fma2(accB[7], qB, q3.y);
        }
#pragma unroll
        for (int d = 0; d < 8; d++) {
            *(float2*)&s_y[p0][2 * d]     = *(float2*)&accA[d];
            *(float2*)&s_y[p0 + 1][2 * d] = *(float2*)&accB[d];
        }
    }
    __syncthreads();

    // cooperative coalesced write: 512 points x 80 floats = 10240 float4
    const float4* f4 = (const float4*)(F + base * NF_);
    float4*       o4 = (float4*)(out + base * OUTW);
#pragma unroll
    for (int i = 0; i < (PPD * OUTW / 4) / 256; i++) {
        int e  = tid + i * 256;
        int pt = e / (OUTW / 4);
        int c  = e % (OUTW / 4);
        float4 v;
        if (c < NF_ / 4) {
            v = f4[pt * (NF_ / 4) + c];
        } else {
            int d = (c - NF_ / 4) * 4;
            v = make_float4(s_y[pt][d], s_y[pt][d + 1], s_y[pt][d + 2], s_y[pt][d + 3]);
        }
        o4[e] = v;
    }
}

// ===========================================================================
extern "C" void kernel_launch(void* const* d_in, const int* in_sizes, int n_in,
                              void* d_out, int out_size)
{
    const float* X   = (const float*)d_in[0];
    const float* F   = (const float*)d_in[1];
    const float* QX  = (const float*)d_in[2];
    const float* omD = (const float*)d_in[3];
    const float* omF = (const float*)d_in[4];
    const float* QW  = (const float*)d_in[5];
    float* out = (float*)d_out;

    kA<<<dim3(NCH, B_), 64>>>(X, F, QX, omD, omF);
    kB<<<dim3(K_, B_), 64>>>(QW);
    kD<<<dim3(M_ / PPD, B_), 256>>>(X, F, QX, omD, out);
}

// round 8
// speedup vs baseline: 1.6504x; 1.0173x over previous
#include <cuda_runtime.h>

// ---------------- problem constants -----------------------------------------
#define B_    16
#define M_    32768
#define K_    85
#define KP    96            // kernel points padded to 8 pairs x 12
#define NF_   64
#define DO_   16
#define NCH   128           // chunks per batch (kernel A)
#define CHPT  (M_ / NCH)    // 256 points per chunk
#define PTS   32            // points per smem tile in kernel A
#define NTILE (CHPT / PTS)  // 8
#define QROW  100           // padded qd row (words)
#define PPD   512           // points per kD block (4 per thread, 128 threads)
#define OUTW  (NF_ + DO_)   // 80
#define LOG2E 1.4426950408889634f

typedef unsigned long long ull;
typedef unsigned int u32;

// ---------------- scratch (device globals: sanctioned no-alloc path) --------
__device__ __align__(16) float g_qf_partial[B_ * NCH * KP * NF_];   // ~50 MB
__device__ __align__(16) float g_P[B_ * K_ * DO_];

__device__ __forceinline__ float ex2f(float x) {
    float y; asm("ex2.approx.ftz.f32 %0, %1;" : "=f"(y) : "f"(x)); return y;
}
// packed fp32x2 FMA (FFMA2; ptxas never auto-fuses — PTX only)
__device__ __forceinline__ void fma2(ull& d, ull a, ull b) {
    asm("fma.rn.f32x2 %0, %1, %2, %0;" : "+l"(d) : "l"(a), "l"(b));
}
__device__ __forceinline__ ull splat2(float x) {
    ull d; u32 u = __float_as_uint(x);
    asm("mov.b64 %0, {%1, %1};" : "=l"(d) : "r"(u)); return d;
}
__device__ __forceinline__ u32 smem_u32(const void* p) {
    u32 a; asm("{.reg .u64 t; cvta.to.shared.u64 t, %1; cvt.u32.u64 %0, t;}"
               : "=r"(a) : "l"(p)); return a;
}
__device__ __forceinline__ void cp16(u32 saddr, const void* g) {
    asm volatile("cp.async.cg.shared.global [%0], [%1], 16;"
                 :: "r"(saddr), "l"(g) : "memory");
}
__device__ __forceinline__ void cp_commit() {
    asm volatile("cp.async.commit_group;" ::: "memory");
}
__device__ __forceinline__ void cp_wait_all() {
    asm volatile("cp.async.wait_group 0;" ::: "memory");
}

// ===========================================================================
// Kernel A: partial QF[b,ch,k,f] = sum_{p in chunk} qd(p,k) * F[p,f]
// 64 threads. Thread (kg,fg) in 8x8 owns 6 k-PAIRS x 8 f (f32x2 over k-pairs:
// a-operand = plain float2 LDS of non-dup qd, b = 8 register splats).
// Double-buffered cp.async pipeline: tile t+1 in flight during tile t.
// (omegaF is applied later, in kB.)
// ===========================================================================
__global__ __launch_bounds__(64, 5)
void kA(const float* __restrict__ X, const float* __restrict__ F,
        const float* __restrict__ QX, const float* __restrict__ omD)
{
    __shared__ __align__(16) float4 s_cst[KP];        // qx',qy',qz',s (log2e-scaled)
    __shared__ float s_c[KP];
    __shared__ __align__(16) float s_f[2][PTS][NF_];  // raw F tiles (cp.async)
    __shared__ __align__(16) float s_xr[2][PTS * 3];  // raw X tiles (cp.async)
    __shared__ __align__(16) float s_qd[2][PTS][QROW];

    const int tid = threadIdx.x;
    const int b   = blockIdx.y;
    const int ch  = blockIdx.x;
    const long base = (long)b * M_ + (long)ch * CHPT;

    // folded per-k constants: arg = c - s*x2 + qx'.x
    for (int e = tid; e < KP; e += 64) {
        float qx = 0.f, qy = 0.f, qz = 0.f, sk = 0.f, ck = -1e30f; // pad -> qd=0
        if (e < K_) {
            qx = QX[e * 3 + 0]; qy = QX[e * 3 + 1]; qz = QX[e * 3 + 2];
            float om = omD[e];
            float inv = 1.0f / (om * om);
            float q2 = qx * qx + qy * qy + qz * qz;
            sk = inv * LOG2E; ck = -q2 * inv * LOG2E;
            float tt = 2.0f * inv * LOG2E;
            qx *= tt; qy *= tt; qz *= tt;
        }
        s_cst[e] = make_float4(qx, qy, qz, sk);
        s_c[e]   = ck;
    }
    // zero qd rows 88..95 in BOTH buffers (phase 2 computes only 0..87)
    for (int e = tid; e < 2 * PTS * 8; e += 64) {
        int bf = e >> 8, r = (e >> 3) & 31, k = 88 + (e & 7);
        s_qd[bf][r][k] = 0.f;
    }

    const int kg = tid >> 3;   // kpair-group: k rows kg*12 .. kg*12+11
    const int fg = tid & 7;    // f cols fg*8 .. fg*8+7

    ull acc[6][8];             // [kpair][f] : lanes = (k0,k1)
#pragma unroll
    for (int i = 0; i < 6; i++)
#pragma unroll
        for (int j = 0; j < 8; j++) acc[i][j] = 0ull;

    // ---- issue tile 0 ----
    {
        const float* gf = F + base * NF_;
        u32 sf = smem_u32(&s_f[0][0][0]);
#pragma unroll
        for (int i = 0; i < 8; i++) {
            int e = tid + i * 64;
            cp16(sf + e * 16, gf + e * 4);
        }
        if (tid < 24)
            cp16(smem_u32(&s_xr[0][0]) + tid * 16, X + base * 3 + tid * 4);
        cp_commit();
    }

    for (int t = 0; t < NTILE; t++) {
        const int bf = t & 1;
        cp_wait_all();
        __syncthreads();                      // tile t data visible to all

        // ---- phase 2: qd tile (X read from raw smem) ----
        {
            const int p2 = tid >> 1;          // 32 points x 2 threads
            const int kh = (tid & 1) * 44;    // covers k 0..87
            float x = s_xr[bf][p2 * 3 + 0];
            float y = s_xr[bf][p2 * 3 + 1];
            float z = s_xr[bf][p2 * 3 + 2];
            float x2 = fmaf(z, z, fmaf(y, y, x * x));
#pragma unroll
            for (int j = 0; j < 22; j++) {
                int k = kh + 2 * j;
                float4 c0 = s_cst[k], c1 = s_cst[k + 1];
                float a0 = fmaf(c0.z, z, fmaf(c0.y, y,
                           fmaf(c0.x, x, fmaf(-c0.w, x2, s_c[k]))));
                float a1 = fmaf(c1.z, z, fmaf(c1.y, y,
                           fmaf(c1.x, x, fmaf(-c1.w, x2, s_c[k + 1]))));
                float2 w; w.x = ex2f(a0); w.y = ex2f(a1);
                *(float2*)&s_qd[bf][p2][k] = w;
            }
        }

        // ---- prefetch tile t+1 (other buffer; safe: all threads passed sync) ----
        if (t + 1 < NTILE) {
            const long p0n = base + (long)(t + 1) * PTS;
            const float* gf = F + p0n * NF_;
            u32 sf = smem_u32(&s_f[1 - bf][0][0]);
#pragma unroll
            for (int i = 0; i < 8; i++) {
                int e = tid + i * 64;
                cp16(sf + e * 16, gf + e * 4);
            }
            if (tid < 24)
                cp16(smem_u32(&s_xr[1 - bf][0]) + tid * 16, X + p0n * 3 + tid * 4);
            cp_commit();
        }
        __syncthreads();                      // qd visible

        // ---- phase 3: rank-PTS update, k-pair-packed f32x2 ----
#pragma unroll 2
        for (int p = 0; p < PTS; ++p) {
            const ulonglong2* ap = (const ulonglong2*)&s_qd[bf][p][kg * 12];
            ulonglong2 A0 = ap[0], A1 = ap[1], A2 = ap[2];  // 6 qd pairs
            const float4* bp = (const float4*)&s_f[bf][p][fg * 8];
            float4 b0 = bp[0], b1 = bp[1];
            ull B0 = splat2(b0.x), B1 = splat2(b0.y), B2 = splat2(b0.z), B3 = splat2(b0.w);
            ull B4 = splat2(b1.x), B5 = splat2(b1.y), B6 = splat2(b1.z), B7 = splat2(b1.w);
            fma2(acc[0][0], A0.x, B0); fma2(acc[0][1], A0.x, B1);
            fma2(acc[0][2], A0.x, B2); fma2(acc[0][3], A0.x, B3);
            fma2(acc[0][4], A0.x, B4); fma2(acc[0][5], A0.x, B5);
            fma2(acc[0][6], A0.x, B6); fma2(acc[0][7], A0.x, B7);
            fma2(acc[1][0], A0.y, B0); fma2(acc[1][1], A0.y, B1);
            fma2(acc[1][2], A0.y, B2); fma2(acc[1][3], A0.y, B3);
            fma2(acc[1][4], A0.y, B4); fma2(acc[1][5], A0.y, B5);
            fma2(acc[1][6], A0.y, B6); fma2(acc[1][7], A0.y, B7);
            fma2(acc[2][0], A1.x, B0); fma2(acc[2][1], A1.x, B1);
            fma2(acc[2][2], A1.x, B2); fma2(acc[2][3], A1.x, B3);
            fma2(acc[2][4], A1.x, B4); fma2(acc[2][5], A1.x, B5);
            fma2(acc[2][6], A1.x, B6); fma2(acc[2][7], A1.x, B7);
            fma2(acc[3][0], A1.y, B0); fma2(acc[3][1], A1.y, B1);
            fma2(acc[3][2], A1.y, B2); fma2(acc[3][3], A1.y, B3);
            fma2(acc[3][4], A1.y, B4); fma2(acc[3][5], A1.y, B5);
            fma2(acc[3][6], A1.y, B6); fma2(acc[3][7], A1.y, B7);
            fma2(acc[4][0], A2.x, B0); fma2(acc[4][1], A2.x, B1);
            fma2(acc[4][2], A2.x, B2); fma2(acc[4][3], A2.x, B3);
            fma2(acc[4][4], A2.x, B4); fma2(acc[4][5], A2.x, B5);
            fma2(acc[4][6], A2.x, B6); fma2(acc[4][7], A2.x, B7);
            fma2(acc[5][0], A2.y, B0); fma2(acc[5][1], A2.y, B1);
            fma2(acc[5][2], A2.y, B2); fma2(acc[5][3], A2.y, B3);
            fma2(acc[5][4], A2.y, B4); fma2(acc[5][5], A2.y, B5);
            fma2(acc[5][6], A2.y, B6); fma2(acc[5][7], A2.y, B7);
        }
        // no trailing sync: next iteration's wait+sync orders buffer reuse
    }

    // ---- epilogue: unpack k-pairs, write 96x64 partial (float4) ----
    const int part = b * NCH + ch;
#pragma unroll
    for (int i = 0; i < 6; i++) {
        int k0 = kg * 12 + 2 * i;
        float2 v0 = *(float2*)&acc[i][0], v1 = *(float2*)&acc[i][1];
        float2 v2 = *(float2*)&acc[i][2], v3 = *(float2*)&acc[i][3];
        float2 v4 = *(float2*)&acc[i][4], v5 = *(float2*)&acc[i][5];
        float2 v6 = *(float2*)&acc[i][6], v7 = *(float2*)&acc[i][7];
        float* d0 = &g_qf_partial[((long)part * KP + k0) * NF_ + fg * 8];
        *(float4*)(d0)       = make_float4(v0.x, v1.x, v2.x, v3.x);
        *(float4*)(d0 + 4)   = make_float4(v4.x, v5.x, v6.x, v7.x);
        float* d1 = d0 + NF_;
        *(float4*)(d1)       = make_float4(v0.y, v1.y, v2.y, v3.y);
        *(float4*)(d1 + 4)   = make_float4(v4.y, v5.y, v6.y, v7.y);
    }
}

// ===========================================================================
// Kernel B: reduce partials over chunks, apply omegaF, project through QW
// -> P[b,k,0:16].  grid (K_, B_), 64 threads.
// ===========================================================================
__global__ __launch_bounds__(64)
void kB(const float* __restrict__ QW, const float* __restrict__ omF)
{
    const int k = blockIdx.x, b = blockIdx.y, f = threadIdx.x;
    const float* p = g_qf_partial + ((long)(b * NCH) * KP + k) * NF_ + f;
    float s = 0.f;
#pragma unroll 8
    for (int c = 0; c < NCH; c++) s += p[(long)c * KP * NF_];

    __shared__ float sq[NF_];
    sq[f] = s * omF[f];            // omegaF folded here (moved out of kA)
    __syncthreads();

    if (f < DO_) {
        float a = 0.f;
#pragma unroll
        for (int j = 0; j < NF_; j++) a = fmaf(sq[j], QW[j * DO_ + f], a);
        g_P[(b * K_ + k) * DO_ + f] = a;
    }
}

// ===========================================================================
// Kernel D: QY[m,:] = sum_k qd(m,k) * P[k,:]; out = concat(F, QY)
// 128 threads, 4 points/thread: P-row LDS amortized 4x -> fma-bound.
// ===========================================================================
__global__ __launch_bounds__(128, 3)
void kD(const float* __restrict__ X, const float* __restrict__ F,
        const float* __restrict__ QX, const float* __restrict__ omD,
        float* __restrict__ out)
{
    __shared__ float s_qx0[K_], s_qx1[K_], s_qx2[K_], s_c[K_], s_s[K_];
    __shared__ __align__(16) float s_P[K_][DO_];        // rows 64B
    __shared__ __align__(16) float s_y[PPD][DO_ + 2];   // rows 72B

    const int tid = threadIdx.x;
    const int b   = blockIdx.y;
    const long base = (long)b * M_ + (long)blockIdx.x * PPD;

    if (tid < K_) {
        float qx = QX[tid * 3 + 0], qy = QX[tid * 3 + 1], qz = QX[tid * 3 + 2];
        float om = omD[tid];
        float inv = 1.0f / (om * om);
        float q2 = qx * qx + qy * qy + qz * qz;
        s_s[tid] = inv * LOG2E;
        s_c[tid] = -q2 * inv * LOG2E;
        float t = 2.0f * inv * LOG2E;
        s_qx0[tid] = qx * t; s_qx1[tid] = qy * t; s_qx2[tid] = qz * t;
    }
    for (int e = tid; e < K_ * DO_; e += 128)
        (&s_P[0][0])[e] = g_P[(long)b * K_ * DO_ + e];
    __syncthreads();

    {
        const int p0 = tid * 4;
        const float4* xp = (const float4*)(X + (base + p0) * 3);  // 48B aligned
        float4 u0 = xp[0], u1 = xp[1], u2 = xp[2];
        float xs[4] = {u0.x, u0.w, u1.z, u2.y};
        float ys[4] = {u0.y, u1.x, u1.w, u2.z};
        float zs[4] = {u0.z, u1.y, u2.x, u2.w};
        float x2s[4];
#pragma unroll
        for (int i = 0; i < 4; i++)
            x2s[i] = fmaf(zs[i], zs[i], fmaf(ys[i], ys[i], xs[i] * xs[i]));

        ull acc[4][8];
#pragma unroll
        for (int i = 0; i < 4; i++)
#pragma unroll
            for (int d = 0; d < 8; d++) acc[i][d] = 0ull;

#pragma unroll 5
        for (int k = 0; k < K_; k++) {
            float c0 = s_qx0[k], c1 = s_qx1[k], c2 = s_qx2[k];
            float sk = s_s[k], ck = s_c[k];
            ull q[4];
#pragma unroll
            for (int i = 0; i < 4; i++) {
                float arg = fmaf(c2, zs[i], fmaf(c1, ys[i],
                            fmaf(c0, xs[i], fmaf(-sk, x2s[i], ck))));
                q[i] = splat2(ex2f(arg));
            }
            const ulonglong2* pr = (const ulonglong2*)&s_P[k][0];  // broadcast
            ulonglong2 r0 = pr[0], r1 = pr[1], r2 = pr[2], r3 = pr[3];
#pragma unroll
            for (int i = 0; i < 4; i++) {
                fma2(acc[i][0], q[i], r0.x); fma2(acc[i][1], q[i], r0.y);
                fma2(acc[i][2], q[i], r1.x); fma2(acc[i][3], q[i], r1.y);
                fma2(acc[i][4], q[i], r2.x); fma2(acc[i][5], q[i], r2.y);
                fma2(acc[i][6], q[i], r3.x); fma2(acc[i][7], q[i], r3.y);
            }
        }
#pragma unroll
        for (int i = 0; i < 4; i++)
#pragma unroll
            for (int d = 0; d < 8; d++)
                *(float2*)&s_y[p0 + i][2 * d] = *(float2*)&acc[i][d];
    }
    __syncthreads();

    // cooperative coalesced write: 512 points x 80 floats = 10240 float4
    const float4* f4 = (const float4*)(F + base * NF_);
    float4*       o4 = (float4*)(out + base * OUTW);
#pragma unroll 8
    for (int i = 0; i < (PPD * OUTW / 4) / 128; i++) {   // 80 iterations
        int e  = tid + i * 128;
        int pt = e / (OUTW / 4);
        int c  = e % (OUTW / 4);
        float4 v;
        if (c < NF_ / 4) {
            v = f4[pt * (NF_ / 4) + c];
        } else {
            int d = (c - NF_ / 4) * 4;
            v = make_float4(s_y[pt][d], s_y[pt][d + 1], s_y[pt][d + 2], s_y[pt][d + 3]);
        }
        o4[e] = v;
    }
}

// ===========================================================================
extern "C" void kernel_launch(void* const* d_in, const int* in_sizes, int n_in,
                              void* d_out, int out_size)
{
    const float* X   = (const float*)d_in[0];
    const float* F   = (const float*)d_in[1];
    const float* QX  = (const float*)d_in[2];
    const float* omD = (const float*)d_in[3];
    const float* omF = (const float*)d_in[4];
    const float* QW  = (const float*)d_in[5];
    float* out = (float*)d_out;

    kA<<<dim3(NCH, B_), 64>>>(X, F, QX, omD);
    kB<<<dim3(K_, B_), 64>>>(QW, omF);
    kD<<<dim3(M_ / PPD, B_), 128>>>(X, F, QX, omD, out);
}